// round 1
// baseline (speedup 1.0000x reference)
#include <cuda_runtime.h>
#include <cstdint>

// Problem constants (fixed shapes from setup_inputs)
#define NB   4
#define NG   4096
#define DXC  2
#define DZC  128
#define NTC  2048
#define NKC  2

// Tile config
#define BT       32                 // t-rows per block
#define BG       64                 // g-chunk
#define WST      (BG*NKC + 2)       // padded weight row stride (floats) = 130
#define NTHREADS 256

#define SMEM_FLOATS (BG*DZC + BT*WST + BT*DXC)   // 8192 + 4160 + 64 = 12416
#define SMEM_BYTES  (SMEM_FLOATS * 4)            // 49664 B (> 48KB -> dynamic + attr)

typedef unsigned long long u64;

__device__ __forceinline__ u64 pack2(float a, float b) {
    u64 r; asm("mov.b64 %0, {%1, %2};" : "=l"(r) : "f"(a), "f"(b)); return r;
}
__device__ __forceinline__ void unpack2(u64 v, float& a, float& b) {
    asm("mov.b64 {%0, %1}, %2;" : "=f"(a), "=f"(b) : "l"(v));
}
__device__ __forceinline__ u64 ffma2(u64 a, u64 b, u64 c) {
    u64 d; asm("fma.rn.f32x2 %0, %1, %2, %3;" : "=l"(d) : "l"(a), "l"(b), "l"(c)); return d;
}
__device__ __forceinline__ float ex2f(float x) {
    float y; asm("ex2.approx.f32 %0, %1;" : "=f"(y) : "f"(x)); return y;
}

// out[b,t,z*NK+k] = sum_g exp(-0.5*sum_d((xt[b,t,d]-xg[b,g,d])/ls[d,k])^2) * zg[b,g,z]
__global__ void __launch_bounds__(NTHREADS)
setconv_kernel(const float* __restrict__ xg_all,
               const float* __restrict__ zg_all,
               const float* __restrict__ xt_all,
               const float* __restrict__ lsp,
               float* __restrict__ out_all)
{
    extern __shared__ float smem[];
    float* zs = smem;                  // [BG][DZC]
    float* ws = smem + BG*DZC;         // [BT][WST] interleaved (w0,w1) pairs
    float* xs = ws + BT*WST;           // [BT][2] xt tile

    const int bid  = blockIdx.x;
    const int b    = bid >> 6;             // NTC/BT = 64 tiles per batch
    const int t0   = (bid & 63) * BT;
    const int tid  = threadIdx.x;

    const float* xgb = xg_all + (size_t)b * NG * DXC;
    const float* zgb = zg_all + (size_t)b * NG * DZC;
    const float* xtb = xt_all + ((size_t)b * NTC + t0) * DXC;
    float*       ob  = out_all + ((size_t)b * NTC + t0) * (DZC * NKC);

    // coefficients c[d][k] = -0.5*log2(e) * (1/ls[d][k])^2 so w = exp2(s0*c0k + s1*c1k)
    const float HL2E = 0.7213475204444817f;   // 0.5 * log2(e)
    float cc[DXC][NKC];
#pragma unroll
    for (int d = 0; d < DXC; ++d)
#pragma unroll
        for (int k = 0; k < NKC; ++k) {
            float p = lsp[d * NKC + k];
            float sp = (p > 20.0f) ? p : log1pf(expf(p));   // softplus
            float inv = 1.0f / (1e-5f + sp);
            cc[d][k] = -HL2E * inv * inv;
        }
    const float c00 = cc[0][0], c10 = cc[1][0];
    const float c01 = cc[0][1], c11 = cc[1][1];

    // stage xt tile (64 floats)
    if (tid < BT * DXC) xs[tid] = xtb[tid];

    // per-thread GEMM assignment: row tl (0..31), z-lane zq (0..7)
    const int tl = tid >> 3;
    const int zq = tid & 7;

    u64 acc0[8], acc1[8];
#pragma unroll
    for (int j = 0; j < 8; ++j) { acc0[j] = 0ULL; acc1[j] = 0ULL; }

    for (int gc = 0; gc < NG / BG; ++gc) {
        __syncthreads();   // protect zs/ws (prev chunk readers, xs on first iter)

        // stage z tile: BG*DZC floats = 2048 float4, 8 per thread, coalesced
        {
            const float4* src = (const float4*)(zgb + (size_t)gc * (BG * DZC));
            float4* dst = (float4*)zs;
#pragma unroll
            for (int i = 0; i < (BG * DZC / 4) / NTHREADS; ++i)
                dst[i * NTHREADS + tid] = src[i * NTHREADS + tid];
        }

        // compute weight tile: 32x64 pairs, 8 per thread
#pragma unroll
        for (int i = 0; i < (BT * BG) / NTHREADS; ++i) {
            int p  = i * NTHREADS + tid;
            int gl = p & (BG - 1);
            int tw = p >> 6;
            float2 xgv = __ldg((const float2*)xgb + gc * BG + gl);
            float2 xtv = ((const float2*)xs)[tw];
            float dx0 = xtv.x - xgv.x;
            float dx1 = xtv.y - xgv.y;
            float s0 = dx0 * dx0;
            float s1 = dx1 * dx1;
            float w0 = ex2f(fmaf(s0, c00, s1 * c10));
            float w1 = ex2f(fmaf(s0, c01, s1 * c11));
            *(float2*)(ws + tw * WST + gl * 2) = make_float2(w0, w1);
        }
        __syncthreads();

        // accumulate: per g: 1 w LDS.64 + 2 packs + 8 z LDS.64 + 16 FFMA2
#pragma unroll 8
        for (int g = 0; g < BG; ++g) {
            const u64* zrow = (const u64*)(zs + g * DZC) + zq;   // z = zq*2 + 16j
            float2 wv = *(const float2*)(ws + tl * WST + g * 2);
            u64 w00 = pack2(wv.x, wv.x);
            u64 w11 = pack2(wv.y, wv.y);
#pragma unroll
            for (int j = 0; j < 8; ++j) {
                u64 zz = zrow[j * 8];
                acc0[j] = ffma2(zz, w00, acc0[j]);
                acc1[j] = ffma2(zz, w11, acc1[j]);
            }
        }
    }

    // epilogue: interleave (z,k) -> out col = z*2 + k, float4 stores (16B aligned)
    float* orow = ob + (size_t)tl * (DZC * NKC);
#pragma unroll
    for (int j = 0; j < 8; ++j) {
        float a0x, a0y, a1x, a1y;
        unpack2(acc0[j], a0x, a0y);
        unpack2(acc1[j], a1x, a1y);
        int z = zq * 2 + j * 16;
        float4 v = make_float4(a0x, a1x, a0y, a1y);
        *(float4*)(orow + z * NKC) = v;
    }
}

extern "C" void kernel_launch(void* const* d_in, const int* in_sizes, int n_in,
                              void* d_out, int out_size)
{
    const float* xg  = (const float*)d_in[0];   // (4,64,64,2)
    const float* zg  = (const float*)d_in[1];   // (4,64,64,128)
    const float* xt  = (const float*)d_in[2];   // (4,2048,2)
    const float* lsp = (const float*)d_in[3];   // (2,2)
    float* out = (float*)d_out;                 // (4,2048,256)

    cudaFuncSetAttribute(setconv_kernel,
                         cudaFuncAttributeMaxDynamicSharedMemorySize, SMEM_BYTES);

    dim3 grid(NB * (NTC / BT));   // 256 blocks
    setconv_kernel<<<grid, NTHREADS, SMEM_BYTES>>>(xg, zg, xt, lsp, out);
}

// round 2
// speedup vs baseline: 1.3284x; 1.3284x over previous
#include <cuda_runtime.h>
#include <cstdint>

// Problem constants (fixed shapes)
#define NB   4
#define NG   4096
#define DXC  2
#define DZC  128
#define NTC  2048
#define NKC  2

// Tile config
#define BT       32      // t-rows per block
#define BG       64      // g-chunk
#define NTHREADS 128     // 16 t-groups (TM=2) x 8 z-groups (TZ=16)

// smem: zs[BG][DZC] + ws[BG][BT/2][4] + xs[BT][2]
#define ZS_FLOATS (BG*DZC)          // 8192
#define WS_FLOATS (BG*(BT/2)*4)     // 4096
#define XS_FLOATS (BT*DXC)          // 64
#define SMEM_BYTES ((ZS_FLOATS + WS_FLOATS + XS_FLOATS) * 4)   // 49408

typedef unsigned long long u64;

__device__ __forceinline__ u64 pack2(float a, float b) {
    u64 r; asm("mov.b64 %0, {%1, %2};" : "=l"(r) : "f"(a), "f"(b)); return r;
}
__device__ __forceinline__ void unpack2(u64 v, float& a, float& b) {
    asm("mov.b64 {%0, %1}, %2;" : "=f"(a), "=f"(b) : "l"(v));
}
__device__ __forceinline__ u64 ffma2(u64 a, u64 b, u64 c) {
    u64 d; asm("fma.rn.f32x2 %0, %1, %2, %3;" : "=l"(d) : "l"(a), "l"(b), "l"(c)); return d;
}
__device__ __forceinline__ float ex2f(float x) {
    float y; asm("ex2.approx.f32 %0, %1;" : "=f"(y) : "f"(x)); return y;
}

__global__ void __launch_bounds__(NTHREADS, 4)
setconv_kernel(const float* __restrict__ xg_all,
               const float* __restrict__ zg_all,
               const float* __restrict__ xt_all,
               const float* __restrict__ lsp,
               float* __restrict__ out_all)
{
    extern __shared__ float smem[];
    float* zs = smem;                          // [BG][DZC]
    float* ws = smem + ZS_FLOATS;              // [BG][16][4]: (t0k0,t0k1,t1k0,t1k1)
    float* xs = ws + WS_FLOATS;                // [BT][2]

    const int bid = blockIdx.x;
    const int b   = bid >> 6;                  // NTC/BT = 64 tiles per batch
    const int t0  = (bid & 63) * BT;
    const int tid = threadIdx.x;

    const float* xgb = xg_all + (size_t)b * NG * DXC;
    const float* zgb = zg_all + (size_t)b * NG * DZC;
    const float* xtb = xt_all + ((size_t)b * NTC + t0) * DXC;
    float*       ob  = out_all + ((size_t)b * NTC + t0) * (DZC * NKC);

    // c[d][k] = -0.5*log2(e) / ls[d][k]^2 ; w = exp2(s0*c0 + s1*c1)
    const float HL2E = 0.7213475204444817f;
    float cc[DXC][NKC];
#pragma unroll
    for (int d = 0; d < DXC; ++d)
#pragma unroll
        for (int k = 0; k < NKC; ++k) {
            float p  = lsp[d * NKC + k];
            float sp = (p > 20.0f) ? p : log1pf(expf(p));
            float inv = 1.0f / (1e-5f + sp);
            cc[d][k] = -HL2E * inv * inv;
        }
    const float c00 = cc[0][0], c10 = cc[1][0];
    const float c01 = cc[0][1], c11 = cc[1][1];

    if (tid < BT * DXC) xs[tid] = xtb[tid];

    const int tg = tid >> 3;    // 0..15  -> t rows tg*2, tg*2+1
    const int zq = tid & 7;     // 0..7   -> z float4 indices zq + 8j

    u64 acc[2][2][8];
#pragma unroll
    for (int t = 0; t < 2; ++t)
#pragma unroll
        for (int k = 0; k < 2; ++k)
#pragma unroll
            for (int j = 0; j < 8; ++j) acc[t][k][j] = 0ULL;

    for (int gc = 0; gc < NG / BG; ++gc) {
        __syncthreads();   // protect zs/ws from prev readers (and xs on iter 0)

        // stage z tile: BG*DZC floats = 2048 float4, 16 per thread, coalesced
        {
            const float4* src = (const float4*)(zgb + (size_t)gc * (BG * DZC));
            float4* dst = (float4*)zs;
#pragma unroll
            for (int i = 0; i < (BG * DZC / 4) / NTHREADS; ++i)
                dst[i * NTHREADS + tid] = src[i * NTHREADS + tid];
        }

        // weight tile: 2048 (t,g) pairs, 16 per thread
#pragma unroll
        for (int i = 0; i < (BT * BG) / NTHREADS; ++i) {
            int p  = i * NTHREADS + tid;
            int tw = p & (BT - 1);
            int gl = p >> 5;
            float2 xgv = __ldg((const float2*)xgb + gc * BG + gl);
            float2 xtv = ((const float2*)xs)[tw];
            float dx0 = xtv.x - xgv.x;
            float dx1 = xtv.y - xgv.y;
            float s0 = dx0 * dx0;
            float s1 = dx1 * dx1;
            float w0 = ex2f(fmaf(s0, c00, s1 * c10));
            float w1 = ex2f(fmaf(s0, c01, s1 * c11));
            // ws float layout: gl*64 + (tw>>1)*4 + (tw&1)*2
            *(float2*)(ws + gl * 64 + tw * 2) = make_float2(w0, w1);
        }
        __syncthreads();

        // accumulate: per g: 1 LDS.128 (w) + 4 packs + 4 LDS.128 (z) + 32 FFMA2
        const float* wsg = ws + tg * 4;
        const float* zsg = zs + zq * 4;
#pragma unroll 4
        for (int g = 0; g < BG; ++g) {
            float4 wv = *(const float4*)(wsg + g * 64);
            u64 w00 = pack2(wv.x, wv.x);
            u64 w01 = pack2(wv.y, wv.y);
            u64 w10 = pack2(wv.z, wv.z);
            u64 w11 = pack2(wv.w, wv.w);
#pragma unroll
            for (int j = 0; j < 4; ++j) {
                float4 z4 = *(const float4*)(zsg + g * DZC + j * 32);
                u64 za = pack2(z4.x, z4.y);
                u64 zb = pack2(z4.z, z4.w);
                acc[0][0][2*j]   = ffma2(za, w00, acc[0][0][2*j]);
                acc[0][0][2*j+1] = ffma2(zb, w00, acc[0][0][2*j+1]);
                acc[0][1][2*j]   = ffma2(za, w01, acc[0][1][2*j]);
                acc[0][1][2*j+1] = ffma2(zb, w01, acc[0][1][2*j+1]);
                acc[1][0][2*j]   = ffma2(za, w10, acc[1][0][2*j]);
                acc[1][0][2*j+1] = ffma2(zb, w10, acc[1][0][2*j+1]);
                acc[1][1][2*j]   = ffma2(za, w11, acc[1][1][2*j]);
                acc[1][1][2*j+1] = ffma2(zb, w11, acc[1][1][2*j+1]);
            }
        }
    }

    // epilogue: out col = z*2 + k ; thread owns z = zq*4+32j .. +3 (j=0..3), t = tg*2, tg*2+1
#pragma unroll
    for (int t = 0; t < 2; ++t) {
        float* orow = ob + (size_t)(tg * 2 + t) * (DZC * NKC);
#pragma unroll
        for (int j = 0; j < 4; ++j) {
            float a0lo, a0hi, a1lo, a1hi, b0lo, b0hi, b1lo, b1hi;
            unpack2(acc[t][0][2*j],   a0lo, a0hi);   // k0: z0,z1
            unpack2(acc[t][1][2*j],   a1lo, a1hi);   // k1: z0,z1
            unpack2(acc[t][0][2*j+1], b0lo, b0hi);   // k0: z2,z3
            unpack2(acc[t][1][2*j+1], b1lo, b1hi);   // k1: z2,z3
            int col = zq * 8 + j * 64;               // = (zq*4 + 32j)*2
            *(float4*)(orow + col)     = make_float4(a0lo, a1lo, a0hi, a1hi);
            *(float4*)(orow + col + 4) = make_float4(b0lo, b1lo, b0hi, b1hi);
        }
    }
}

extern "C" void kernel_launch(void* const* d_in, const int* in_sizes, int n_in,
                              void* d_out, int out_size)
{
    const float* xg  = (const float*)d_in[0];
    const float* zg  = (const float*)d_in[1];
    const float* xt  = (const float*)d_in[2];
    const float* lsp = (const float*)d_in[3];
    float* out = (float*)d_out;

    cudaFuncSetAttribute(setconv_kernel,
                         cudaFuncAttributeMaxDynamicSharedMemorySize, SMEM_BYTES);

    dim3 grid(NB * (NTC / BT));   // 256 blocks
    setconv_kernel<<<grid, NTHREADS, SMEM_BYTES>>>(xg, zg, xt, lsp, out);
}

// round 4
// speedup vs baseline: 4.1645x; 3.1350x over previous
#include <cuda_runtime.h>
#include <cstdint>

// Shapes (fixed)
#define NB 4
#define NG 4096
#define DZ 128
#define NT 2048

// Tiling
#define MT 64            // t rows per CTA
#define GC 64            // g per staged chunk
#define NCHUNK (NG/GC)   // 64
#define ZROW 132         // padded smem row stride (floats)
#define NTHREADS 256     // 8 warps: (k in {0,1}) x (4 t-subtiles of 16)

typedef unsigned int u32;

__device__ __forceinline__ float ex2f(float x) {
    float y; asm("ex2.approx.f32 %0, %1;" : "=f"(y) : "f"(x)); return y;
}
__device__ __forceinline__ u32 cvt_tf32(float x) {
    u32 y; asm("cvt.rna.tf32.f32 %0, %1;" : "=r"(y) : "f"(x)); return y;
}

// out[b,t,z*2+k] = sum_g exp(-0.5*sum_d((xt-xg)/ls_dk)^2) * zg[b,g,z]
__global__ void __launch_bounds__(NTHREADS, 1)
setconv_mma(const float* __restrict__ xg_all,
            const float* __restrict__ zg_all,
            const float* __restrict__ xt_all,
            const float* __restrict__ lsp,
            float* __restrict__ out_all)
{
    __shared__ u32   zsm[GC * ZROW];   // permuted tf32 Z tile: 33792 B
    __shared__ float xgs[GC * 2];      // xg chunk

    const int cta  = blockIdx.x;        // 128 CTAs
    const int b    = cta >> 5;
    const int t0   = (cta & 31) * MT;
    const int tid  = threadIdx.x;
    const int w    = tid >> 5;
    const int lane = tid & 31;
    const int kk   = w >> 2;            // kernel index for this warp
    const int tsub = w & 3;             // 16-row t subtile
    const int q    = lane >> 2;         // fragment group id (0..7)
    const int r4   = lane & 3;          // fragment thread-in-group (0..3)

    // RBF coefficients for this warp's k: c_d = -0.5*log2(e)/ls_d^2
    float cc0, cc1;
    {
        const float HL2E = 0.7213475204444817f;
        float p0 = lsp[0 * 2 + kk], p1 = lsp[1 * 2 + kk];
        float sp0 = (p0 > 20.f) ? p0 : log1pf(expf(p0));
        float sp1 = (p1 > 20.f) ? p1 : log1pf(expf(p1));
        float i0 = 1.f / (1e-5f + sp0), i1 = 1.f / (1e-5f + sp1);
        cc0 = -HL2E * i0 * i0;
        cc1 = -HL2E * i1 * i1;
    }

    // This thread's two t rows (mma A-fragment rows: q and q+8)
    const int tA = t0 + tsub * 16 + q;
    const int tB = tA + 8;
    const float2 xA = ((const float2*)xt_all)[(size_t)b * NT + tA];
    const float2 xB = ((const float2*)xt_all)[(size_t)b * NT + tB];

    // Accumulators: 16 n-tiles (8 z each) x 4 regs
    float c[16][4];
#pragma unroll
    for (int j = 0; j < 16; ++j) {
        c[j][0] = 0.f; c[j][1] = 0.f; c[j][2] = 0.f; c[j][3] = 0.f;
    }

    for (int gc = 0; gc < NCHUNK; ++gc) {
        __syncthreads();   // previous chunk's readers done

        // stage xg chunk (64 x float2)
        if (tid < GC * 2) xgs[tid] = xg_all[((size_t)b * NG + gc * GC) * 2 + tid];

        // stage Z chunk permuted: zsm[g][(z&7)*16 + (z>>3)], RN->tf32
        const float4* zsrc = (const float4*)(zg_all + ((size_t)b * NG + gc * GC) * DZ);
#pragma unroll
        for (int i = 0; i < 8; ++i) {
            int idx = i * NTHREADS + tid;      // 2048 float4 per chunk
            int gl  = idx >> 5;                // row (32 float4 per row)
            int c4  = idx & 31;
            float4 v = __ldg(zsrc + idx);
            int z0 = c4 * 4;
            u32* dst = zsm + gl * ZROW;
            dst[((z0    ) & 7) * 16 + ((z0    ) >> 3)] = cvt_tf32(v.x);
            dst[((z0 + 1) & 7) * 16 + ((z0 + 1) >> 3)] = cvt_tf32(v.y);
            dst[((z0 + 2) & 7) * 16 + ((z0 + 2) >> 3)] = cvt_tf32(v.z);
            dst[((z0 + 3) & 7) * 16 + ((z0 + 3) >> 3)] = cvt_tf32(v.w);
        }
        __syncthreads();

        // 8 k-slices of 8 g each
#pragma unroll
        for (int s = 0; s < 8; ++s) {
            // A fragment: weights computed in-register at fragment coords
            float2 xg0 = ((const float2*)xgs)[s * 8 + r4];       // g col r4
            float2 xg1 = ((const float2*)xgs)[s * 8 + r4 + 4];   // g col r4+4
            u32 a0, a1, a2, a3;
            {
                float d0, d1, s0, s1;
                d0 = xA.x - xg0.x; d1 = xA.y - xg0.y; s0 = d0 * d0; s1 = d1 * d1;
                a0 = cvt_tf32(ex2f(fmaf(s0, cc0, s1 * cc1)));
                d0 = xB.x - xg0.x; d1 = xB.y - xg0.y; s0 = d0 * d0; s1 = d1 * d1;
                a1 = cvt_tf32(ex2f(fmaf(s0, cc0, s1 * cc1)));
                d0 = xA.x - xg1.x; d1 = xA.y - xg1.y; s0 = d0 * d0; s1 = d1 * d1;
                a2 = cvt_tf32(ex2f(fmaf(s0, cc0, s1 * cc1)));
                d0 = xB.x - xg1.x; d1 = xB.y - xg1.y; s0 = d0 * d0; s1 = d1 * d1;
                a3 = cvt_tf32(ex2f(fmaf(s0, cc0, s1 * cc1)));
            }

            // B fragments: 8 conflict-free LDS.128 covering all 16 n-tiles
            const uint4* bu_p = (const uint4*)(zsm + (s * 8 + r4    ) * ZROW + q * 16);
            const uint4* bl_p = (const uint4*)(zsm + (s * 8 + r4 + 4) * ZROW + q * 16);
            uint4 bu[4], bl[4];
#pragma unroll
            for (int i = 0; i < 4; ++i) { bu[i] = bu_p[i]; bl[i] = bl_p[i]; }

#pragma unroll
            for (int j = 0; j < 16; ++j) {
                u32 b0 = ((const u32*)bu)[j];
                u32 b1 = ((const u32*)bl)[j];
                asm volatile(
                    "mma.sync.aligned.m16n8k8.row.col.f32.tf32.tf32.f32 "
                    "{%0,%1,%2,%3}, {%4,%5,%6,%7}, {%8,%9}, {%0,%1,%2,%3};"
                    : "+f"(c[j][0]), "+f"(c[j][1]), "+f"(c[j][2]), "+f"(c[j][3])
                    : "r"(a0), "r"(a1), "r"(a2), "r"(a3), "r"(b0), "r"(b1));
            }
        }
    }

    // epilogue: C(row, n) -> out[b, t, n*2 + kk]; z = 8j + 2*r4 (+1)
    float* oA = out_all + ((size_t)b * NT + tA) * (DZ * 2) + kk;
    float* oB = out_all + ((size_t)b * NT + tB) * (DZ * 2) + kk;
#pragma unroll
    for (int j = 0; j < 16; ++j) {
        int n0 = j * 16 + r4 * 4;   // (8j + 2*r4) * 2
        oA[n0]     = c[j][0];
        oA[n0 + 2] = c[j][1];
        oB[n0]     = c[j][2];
        oB[n0 + 2] = c[j][3];
    }
}

extern "C" void kernel_launch(void* const* d_in, const int* in_sizes, int n_in,
                              void* d_out, int out_size)
{
    const float* xg  = (const float*)d_in[0];   // (4,64,64,2)
    const float* zg  = (const float*)d_in[1];   // (4,64,64,128)
    const float* xt  = (const float*)d_in[2];   // (4,2048,2)
    const float* lsp = (const float*)d_in[3];   // (2,2)
    float* out = (float*)d_out;                 // (4,2048,256)

    setconv_mma<<<NB * (NT / MT), NTHREADS>>>(xg, zg, xt, lsp, out);
}

// round 5
// speedup vs baseline: 5.9857x; 1.4373x over previous
#include <cuda_runtime.h>
#include <cstdint>

// Shapes (fixed)
#define NB 4
#define NG 4096
#define DZ 128
#define NT 2048

// Tiling
#define MT 32            // t rows per CTA
#define GC 64            // g per staged chunk
#define NCHUNK (NG/GC)   // 64
#define ZROW 132         // smem row stride (u32) for g-pair rows
#define NTHREADS 256     // 8 warps: 2 tsub x 2 k x 2 gsplit

typedef unsigned int u32;

__device__ __forceinline__ float ex2f(float x) {
    float y; asm("ex2.approx.f32 %0, %1;" : "=f"(y) : "f"(x)); return y;
}
// pack two f32 -> f16x2 {lo, hi}
__device__ __forceinline__ u32 f16x2(float lo, float hi) {
    u32 d; asm("cvt.rn.f16x2.f32 %0, %1, %2;" : "=r"(d) : "f"(hi), "f"(lo)); return d;
}

__global__ void __launch_bounds__(NTHREADS, 2)
setconv_h(const float* __restrict__ xg_all,
          const float* __restrict__ zg_all,
          const float* __restrict__ xt_all,
          const float* __restrict__ lsp,
          float* __restrict__ out_all)
{
    // sred: reused as (a) staged Z tile zsm[32][ZROW] u32 (16.5KB) during mainloop,
    //       (b) 32KB float4 reduction buffer in the epilogue. xgs lives at the tail.
    __shared__ __align__(16) float sred[8192 + 128];
    u32*   zsm = (u32*)sred;            // [gpair 0..31][ZROW]
    float* xgs = sred + 8192;           // 64 x float2

    const int cta  = blockIdx.x;        // 256 CTAs
    const int b    = cta >> 6;
    const int t0   = (cta & 63) * MT;
    const int tid  = threadIdx.x;
    const int w    = tid >> 5;
    const int lane = tid & 31;
    const int tsub = w >> 2;            // 0..1
    const int kk   = (w >> 1) & 1;      // RBF kernel index
    const int gs   = w & 1;             // g-split half
    const int q    = lane >> 2;         // 0..7
    const int r    = lane & 3;          // 0..3

    // RBF coefficients for this warp's k: c_d = -0.5*log2(e)/ls_d^2
    float cc0, cc1;
    {
        const float HL2E = 0.7213475204444817f;
        float p0 = lsp[0 * 2 + kk], p1 = lsp[1 * 2 + kk];
        float sp0 = (p0 > 20.f) ? p0 : log1pf(expf(p0));
        float sp1 = (p1 > 20.f) ? p1 : log1pf(expf(p1));
        float i0 = 1.f / (1e-5f + sp0), i1 = 1.f / (1e-5f + sp1);
        cc0 = -HL2E * i0 * i0;
        cc1 = -HL2E * i1 * i1;
    }

    const int tA = t0 + tsub * 16 + q;
    const int tB = tA + 8;
    const float2 xA = ((const float2*)xt_all)[(size_t)b * NT + tA];
    const float2 xB = ((const float2*)xt_all)[(size_t)b * NT + tB];

    float c[16][4];
#pragma unroll
    for (int j = 0; j < 16; ++j) { c[j][0]=0.f; c[j][1]=0.f; c[j][2]=0.f; c[j][3]=0.f; }

    for (int gc = 0; gc < NCHUNK; ++gc) {
        __syncthreads();   // previous chunk readers done with zsm

        if (tid < GC * 2) xgs[tid] = xg_all[((size_t)b * NG + gc * GC) * 2 + tid];

        // stage Z: g-pair packed f16x2, j-permuted: zsm[gp][ (z&7)*16 + (z>>3) ]
        const float* zbase = zg_all + ((size_t)b * NG + gc * GC) * DZ;
        const int z4 = lane;                       // float4 col within row
#pragma unroll
        for (int it = 0; it < 4; ++it) {
            int gp = w + it * 8;                   // 0..31
            float4 v0 = __ldg((const float4*)(zbase + (size_t)(2 * gp)     * DZ) + z4);
            float4 v1 = __ldg((const float4*)(zbase + (size_t)(2 * gp + 1) * DZ) + z4);
            u32* dst = zsm + gp * ZROW;
            int p0 = (z4 & 1) * 64 + (z4 >> 1);    // p(z)=64(z4&1)+16e+(z4>>1)
            dst[p0]      = f16x2(v0.x, v1.x);
            dst[p0 + 16] = f16x2(v0.y, v1.y);
            dst[p0 + 32] = f16x2(v0.z, v1.z);
            dst[p0 + 48] = f16x2(v0.w, v1.w);
        }
        __syncthreads();

        // 2 slices of 16 g for this warp's g-split
#pragma unroll
        for (int i = 0; i < 2; ++i) {
            const int s = gs + 2 * i;

            // B fragments: 8 conflict-free LDS.128
            const uint4* bup = (const uint4*)(zsm + (s * 8 + r)     * ZROW + q * 16);
            const uint4* blp = (const uint4*)(zsm + (s * 8 + r + 4) * ZROW + q * 16);
            uint4 BU[4], BL[4];
#pragma unroll
            for (int m = 0; m < 4; ++m) { BU[m] = bup[m]; BL[m] = blp[m]; }

            // A fragment: 8 RBF weights at exact fragment coords
            const float4* xg4 = (const float4*)xgs;
            float4 ga = xg4[s * 8 + r];        // cols s*16+2r, +1  (x,y | z,w)
            float4 gb = xg4[s * 8 + r + 4];    // cols s*16+2r+8, +9
            float d0, d1, s0, s1, wA0, wA1, wB0, wB1, wA2, wA3, wB2, wB3;
            d0 = xA.x - ga.x; d1 = xA.y - ga.y; s0 = d0*d0; s1 = d1*d1;
            wA0 = ex2f(fmaf(s0, cc0, s1 * cc1));
            d0 = xA.x - ga.z; d1 = xA.y - ga.w; s0 = d0*d0; s1 = d1*d1;
            wA1 = ex2f(fmaf(s0, cc0, s1 * cc1));
            d0 = xB.x - ga.x; d1 = xB.y - ga.y; s0 = d0*d0; s1 = d1*d1;
            wB0 = ex2f(fmaf(s0, cc0, s1 * cc1));
            d0 = xB.x - ga.z; d1 = xB.y - ga.w; s0 = d0*d0; s1 = d1*d1;
            wB1 = ex2f(fmaf(s0, cc0, s1 * cc1));
            d0 = xA.x - gb.x; d1 = xA.y - gb.y; s0 = d0*d0; s1 = d1*d1;
            wA2 = ex2f(fmaf(s0, cc0, s1 * cc1));
            d0 = xA.x - gb.z; d1 = xA.y - gb.w; s0 = d0*d0; s1 = d1*d1;
            wA3 = ex2f(fmaf(s0, cc0, s1 * cc1));
            d0 = xB.x - gb.x; d1 = xB.y - gb.y; s0 = d0*d0; s1 = d1*d1;
            wB2 = ex2f(fmaf(s0, cc0, s1 * cc1));
            d0 = xB.x - gb.z; d1 = xB.y - gb.w; s0 = d0*d0; s1 = d1*d1;
            wB3 = ex2f(fmaf(s0, cc0, s1 * cc1));
            u32 a0 = f16x2(wA0, wA1);
            u32 a1 = f16x2(wB0, wB1);
            u32 a2 = f16x2(wA2, wA3);
            u32 a3 = f16x2(wB2, wB3);

#pragma unroll
            for (int j = 0; j < 16; ++j) {
                u32 b0 = ((const u32*)BU)[j];
                u32 b1 = ((const u32*)BL)[j];
                asm volatile(
                    "mma.sync.aligned.m16n8k16.row.col.f32.f16.f16.f32 "
                    "{%0,%1,%2,%3}, {%4,%5,%6,%7}, {%8,%9}, {%0,%1,%2,%3};"
                    : "+f"(c[j][0]), "+f"(c[j][1]), "+f"(c[j][2]), "+f"(c[j][3])
                    : "r"(a0), "r"(a1), "r"(a2), "r"(a3), "r"(b0), "r"(b1));
            }
        }
    }

    // ---- reduce g-split pairs via smem, then store ----
    __syncthreads();
    float4* red = (float4*)sred;       // [j 0..15][slot 0..3][lane 0..31]
    const int slot = w >> 1;
    if (gs == 1) {
#pragma unroll
        for (int j = 0; j < 16; ++j)
            red[j * 128 + slot * 32 + lane] = make_float4(c[j][0], c[j][1], c[j][2], c[j][3]);
    }
    __syncthreads();
    if (gs == 0) {
        float* oA = out_all + ((size_t)b * NT + tA) * (DZ * 2) + kk;
        float* oB = out_all + ((size_t)b * NT + tB) * (DZ * 2) + kk;
#pragma unroll
        for (int j = 0; j < 16; ++j) {
            float4 v = red[j * 128 + slot * 32 + lane];
            int n0 = 16 * j + 4 * r;   // out col (minus kk): z = 8j + 2r (+e)
            oA[n0]     = c[j][0] + v.x;
            oA[n0 + 2] = c[j][1] + v.y;
            oB[n0]     = c[j][2] + v.z;
            oB[n0 + 2] = c[j][3] + v.w;
        }
    }
}

extern "C" void kernel_launch(void* const* d_in, const int* in_sizes, int n_in,
                              void* d_out, int out_size)
{
    const float* xg  = (const float*)d_in[0];   // (4,64,64,2)
    const float* zg  = (const float*)d_in[1];   // (4,64,64,128)
    const float* xt  = (const float*)d_in[2];   // (4,2048,2)
    const float* lsp = (const float*)d_in[3];   // (2,2)
    float* out = (float*)d_out;                 // (4,2048,256)

    setconv_h<<<NB * (NT / MT), NTHREADS>>>(xg, zg, xt, lsp, out);
}

// round 6
// speedup vs baseline: 7.3283x; 1.2243x over previous
#include <cuda_runtime.h>
#include <cstdint>

// Shapes (fixed)
#define NB 4
#define NG 4096
#define DZ 128
#define NT 2048

// Tiling
#define MT 32              // t rows per CTA
#define GC 64              // g per chunk
#define NCHUNK (NG/GC)     // 64
#define ZROW 132           // u32 stride per g-pair row (pad 4 -> conflict-free)
#define TILE_U32 (32*ZROW + 128)    // 4352: z part + xg tail (64 float2)
#define TILE_BYTES (TILE_U32*4)     // 17408
#define NSEG (TILE_BYTES/16)        // 1088 16B segments
#define NTHREADS 256

typedef unsigned int u32;

// Pre-packed Z tiles: [b][chunk][ gp rows x ZROW f16x2 | xg 128 floats ]  (~4.25 MB)
__device__ __align__(16) u32 g_Zh[(size_t)NB * NCHUNK * TILE_U32];

__device__ __forceinline__ float ex2f(float x) {
    float y; asm("ex2.approx.f32 %0, %1;" : "=f"(y) : "f"(x)); return y;
}
__device__ __forceinline__ u32 f16x2(float lo, float hi) {
    u32 d; asm("cvt.rn.f16x2.f32 %0, %1, %2;" : "=r"(d) : "f"(hi), "f"(lo)); return d;
}
__device__ __forceinline__ u32 smem_u32(const void* p) {
    u32 a;
    asm("{ .reg .u64 t; cvta.to.shared.u64 t, %1; cvt.u32.u64 %0, t; }" : "=r"(a) : "l"(p));
    return a;
}

// ---------------- prep: pack Z (f16x2, g-pairs, j-permuted) + xg per chunk ----
__global__ void __launch_bounds__(NTHREADS)
prep_tiles(const float* __restrict__ zg_all, const float* __restrict__ xg_all)
{
    const int bc  = blockIdx.x;          // b*NCHUNK + chunk
    const int b   = bc >> 6;
    const int gc  = bc & 63;
    const int tid = threadIdx.x;
    const int w   = tid >> 5;
    const int z4  = tid & 31;

    u32* tile = g_Zh + (size_t)bc * TILE_U32;
    const float* zbase = zg_all + ((size_t)b * NG + gc * GC) * DZ;

#pragma unroll
    for (int it = 0; it < 4; ++it) {
        int gp = w + it * 8;             // 0..31 (g-pair)
        float4 v0 = __ldg((const float4*)(zbase + (size_t)(2 * gp)     * DZ) + z4);
        float4 v1 = __ldg((const float4*)(zbase + (size_t)(2 * gp + 1) * DZ) + z4);
        u32* dst = tile + gp * ZROW;
        int p0 = (z4 & 1) * 64 + (z4 >> 1);     // perm p(z)=(z&7)*16+(z>>3)
        dst[p0]      = f16x2(v0.x, v1.x);
        dst[p0 + 16] = f16x2(v0.y, v1.y);
        dst[p0 + 32] = f16x2(v0.z, v1.z);
        dst[p0 + 48] = f16x2(v0.w, v1.w);
    }
    if (tid < 128)
        tile[32 * ZROW + tid] =
            ((const u32*)xg_all)[((size_t)b * NG + gc * GC) * 2 + tid];
}

// ---------------- main: weights-in-register + HMMA, cp.async double buffer ----
__global__ void __launch_bounds__(NTHREADS, 2)
setconv_h(const float* __restrict__ xt_all,
          const float* __restrict__ lsp,
          float* __restrict__ out_all)
{
    __shared__ __align__(16) u32 smem[2 * TILE_U32];   // 34816 B; reused as red buf

    const int cta  = blockIdx.x;        // 256 CTAs
    const int b    = cta >> 6;
    const int t0   = (cta & 63) * MT;
    const int tid  = threadIdx.x;
    const int w    = tid >> 5;
    const int lane = tid & 31;
    const int tsub = w >> 2;            // 0..1
    const int kk   = (w >> 1) & 1;      // RBF kernel index
    const int gs   = w & 1;             // g-split half
    const int q    = lane >> 2;         // 0..7
    const int r    = lane & 3;          // 0..3

    const u32 sbase = smem_u32(smem);
    const char* gtiles = (const char*)(g_Zh + (size_t)b * NCHUNK * TILE_U32);

    // RBF coefficients
    float cc0, cc1;
    {
        const float HL2E = 0.7213475204444817f;
        float p0 = lsp[0 * 2 + kk], p1 = lsp[1 * 2 + kk];
        float sp0 = (p0 > 20.f) ? p0 : log1pf(expf(p0));
        float sp1 = (p1 > 20.f) ? p1 : log1pf(expf(p1));
        float i0 = 1.f / (1e-5f + sp0), i1 = 1.f / (1e-5f + sp1);
        cc0 = -HL2E * i0 * i0;
        cc1 = -HL2E * i1 * i1;
    }

    const int tA = t0 + tsub * 16 + q;
    const int tB = tA + 8;
    const float2 xA = ((const float2*)xt_all)[(size_t)b * NT + tA];
    const float2 xB = ((const float2*)xt_all)[(size_t)b * NT + tB];

    float c[16][4];
#pragma unroll
    for (int j = 0; j < 16; ++j) { c[j][0]=0.f; c[j][1]=0.f; c[j][2]=0.f; c[j][3]=0.f; }

    // prologue: stage chunk 0
    {
        const char* src = gtiles;
#pragma unroll
        for (int i = 0; i < 5; ++i) {
            int seg = tid + i * NTHREADS;
            if (seg < NSEG)
                asm volatile("cp.async.cg.shared.global [%0], [%1], 16;"
                             :: "r"(sbase + seg * 16), "l"(src + seg * 16) : "memory");
        }
        asm volatile("cp.async.commit_group;" ::: "memory");
    }

    for (int gc = 0; gc < NCHUNK; ++gc) {
        asm volatile("cp.async.wait_group 0;" ::: "memory");
        __syncthreads();   // chunk gc visible; all warps done with stage (gc+1)&1

        if (gc + 1 < NCHUNK) {
            const char* src = gtiles + (size_t)(gc + 1) * TILE_BYTES;
            u32 dsts = sbase + ((gc + 1) & 1) * TILE_BYTES;
#pragma unroll
            for (int i = 0; i < 5; ++i) {
                int seg = tid + i * NTHREADS;
                if (seg < NSEG)
                    asm volatile("cp.async.cg.shared.global [%0], [%1], 16;"
                                 :: "r"(dsts + seg * 16), "l"(src + seg * 16) : "memory");
            }
            asm volatile("cp.async.commit_group;" ::: "memory");
        }

        const u32*    zsm = smem + (gc & 1) * TILE_U32;
        const float4* xg4 = (const float4*)(zsm + 32 * ZROW);

#pragma unroll
        for (int i = 0; i < 2; ++i) {
            const int s = gs + 2 * i;

            // B fragments: 8 conflict-free LDS.128
            const uint4* bup = (const uint4*)(zsm + (s * 8 + r)     * ZROW + q * 16);
            const uint4* blp = (const uint4*)(zsm + (s * 8 + r + 4) * ZROW + q * 16);
            uint4 BU[4], BL[4];
#pragma unroll
            for (int m = 0; m < 4; ++m) { BU[m] = bup[m]; BL[m] = blp[m]; }

            // A fragment: 8 RBF weights at fragment coords
            float4 ga = xg4[s * 8 + r];
            float4 gb = xg4[s * 8 + r + 4];
            float d0, d1, s0, s1, wA0, wA1, wB0, wB1, wA2, wA3, wB2, wB3;
            d0 = xA.x - ga.x; d1 = xA.y - ga.y; s0 = d0*d0; s1 = d1*d1;
            wA0 = ex2f(fmaf(s0, cc0, s1 * cc1));
            d0 = xA.x - ga.z; d1 = xA.y - ga.w; s0 = d0*d0; s1 = d1*d1;
            wA1 = ex2f(fmaf(s0, cc0, s1 * cc1));
            d0 = xB.x - ga.x; d1 = xB.y - ga.y; s0 = d0*d0; s1 = d1*d1;
            wB0 = ex2f(fmaf(s0, cc0, s1 * cc1));
            d0 = xB.x - ga.z; d1 = xB.y - ga.w; s0 = d0*d0; s1 = d1*d1;
            wB1 = ex2f(fmaf(s0, cc0, s1 * cc1));
            d0 = xA.x - gb.x; d1 = xA.y - gb.y; s0 = d0*d0; s1 = d1*d1;
            wA2 = ex2f(fmaf(s0, cc0, s1 * cc1));
            d0 = xA.x - gb.z; d1 = xA.y - gb.w; s0 = d0*d0; s1 = d1*d1;
            wA3 = ex2f(fmaf(s0, cc0, s1 * cc1));
            d0 = xB.x - gb.x; d1 = xB.y - gb.y; s0 = d0*d0; s1 = d1*d1;
            wB2 = ex2f(fmaf(s0, cc0, s1 * cc1));
            d0 = xB.x - gb.z; d1 = xB.y - gb.w; s0 = d0*d0; s1 = d1*d1;
            wB3 = ex2f(fmaf(s0, cc0, s1 * cc1));
            u32 a0 = f16x2(wA0, wA1);
            u32 a1 = f16x2(wB0, wB1);
            u32 a2 = f16x2(wA2, wA3);
            u32 a3 = f16x2(wB2, wB3);

#pragma unroll
            for (int j = 0; j < 16; ++j) {
                u32 b0 = ((const u32*)BU)[j];
                u32 b1 = ((const u32*)BL)[j];
                asm volatile(
                    "mma.sync.aligned.m16n8k16.row.col.f32.f16.f16.f32 "
                    "{%0,%1,%2,%3}, {%4,%5,%6,%7}, {%8,%9}, {%0,%1,%2,%3};"
                    : "+f"(c[j][0]), "+f"(c[j][1]), "+f"(c[j][2]), "+f"(c[j][3])
                    : "r"(a0), "r"(a1), "r"(a2), "r"(a3), "r"(b0), "r"(b1));
            }
        }
    }

    // ---- reduce g-split pairs via smem, then store ----
    __syncthreads();
    float4* red = (float4*)smem;       // 32KB needed <= 34816 available
    const int slot = w >> 1;
    if (gs == 1) {
#pragma unroll
        for (int j = 0; j < 16; ++j)
            red[j * 128 + slot * 32 + lane] = make_float4(c[j][0], c[j][1], c[j][2], c[j][3]);
    }
    __syncthreads();
    if (gs == 0) {
        float* oA = out_all + ((size_t)b * NT + tA) * (DZ * 2) + kk;
        float* oB = out_all + ((size_t)b * NT + tB) * (DZ * 2) + kk;
#pragma unroll
        for (int j = 0; j < 16; ++j) {
            float4 v = red[j * 128 + slot * 32 + lane];
            int n0 = 16 * j + 4 * r;
            oA[n0]     = c[j][0] + v.x;
            oA[n0 + 2] = c[j][1] + v.y;
            oB[n0]     = c[j][2] + v.z;
            oB[n0 + 2] = c[j][3] + v.w;
        }
    }
}

extern "C" void kernel_launch(void* const* d_in, const int* in_sizes, int n_in,
                              void* d_out, int out_size)
{
    const float* xg  = (const float*)d_in[0];   // (4,64,64,2)
    const float* zg  = (const float*)d_in[1];   // (4,64,64,128)
    const float* xt  = (const float*)d_in[2];   // (4,2048,2)
    const float* lsp = (const float*)d_in[3];   // (2,2)
    float* out = (float*)d_out;                 // (4,2048,256)

    prep_tiles<<<NB * NCHUNK, NTHREADS>>>(zg, xg);
    setconv_h<<<NB * (NT / MT), NTHREADS>>>(xt, lsp, out);
}

// round 7
// speedup vs baseline: 7.6033x; 1.0375x over previous
#include <cuda_runtime.h>
#include <cstdint>

// Shapes (fixed)
#define NB 4
#define NG 4096
#define DZ 128
#define NT 2048

// Tiling
#define MT 32              // t rows per CTA
#define GC 64              // g per chunk
#define NCHUNK (NG/GC)     // 64
#define ZROW 132           // u32 stride per g-pair row (pad 4 -> conflict-free)
#define TILE_U32 (32*ZROW + 256)    // 4480: Z part + gmeta (64 float4)
#define TILE_BYTES (TILE_U32*4)     // 17920 = 224 threads x 5 x 16B
#define NTHREADS 256

typedef unsigned int u32;

// Pre-packed tiles: [b][chunk][ Z f16x2 32xZROW | gmeta 64 x {xg0,xg1,Bg0,Bg1} ]
__device__ __align__(16) u32 g_Zh[(size_t)NB * NCHUNK * TILE_U32];

__device__ __forceinline__ float ex2f(float x) {
    float y; asm("ex2.approx.f32 %0, %1;" : "=f"(y) : "f"(x)); return y;
}
__device__ __forceinline__ u32 f16x2(float lo, float hi) {
    u32 d; asm("cvt.rn.f16x2.f32 %0, %1, %2;" : "=r"(d) : "f"(hi), "f"(lo)); return d;
}
__device__ __forceinline__ u32 smem_u32(const void* p) {
    u32 a;
    asm("{ .reg .u64 t; cvta.to.shared.u64 t, %1; cvt.u32.u64 %0, t; }" : "=r"(a) : "l"(p));
    return a;
}

// ---------------- prep: pack Z (f16x2, g-pairs, j-permuted) + gmeta ----------
__global__ void __launch_bounds__(NTHREADS)
prep_tiles(const float* __restrict__ zg_all, const float* __restrict__ xg_all,
           const float* __restrict__ lsp)
{
    const int bc  = blockIdx.x;          // b*NCHUNK + chunk
    const int b   = bc >> 6;
    const int gc  = bc & 63;
    const int tid = threadIdx.x;
    const int w   = tid >> 5;
    const int z4  = tid & 31;

    u32* tile = g_Zh + (size_t)bc * TILE_U32;
    const float* zbase = zg_all + ((size_t)b * NG + gc * GC) * DZ;

#pragma unroll
    for (int it = 0; it < 4; ++it) {
        int gp = w + it * 8;             // 0..31 (g-pair)
        float4 v0 = __ldg((const float4*)(zbase + (size_t)(2 * gp)     * DZ) + z4);
        float4 v1 = __ldg((const float4*)(zbase + (size_t)(2 * gp + 1) * DZ) + z4);
        u32* dst = tile + gp * ZROW;
        int p0 = (z4 & 1) * 64 + (z4 >> 1);     // perm p(z)=(z&7)*16+(z>>3)
        dst[p0]      = f16x2(v0.x, v1.x);
        dst[p0 + 16] = f16x2(v0.y, v1.y);
        dst[p0 + 32] = f16x2(v0.z, v1.z);
        dst[p0 + 48] = f16x2(v0.w, v1.w);
    }

    // gmeta: per g {xg0, xg1, Bg_k0, Bg_k1}, Bg_k = ck0*xg0^2 + ck1*xg1^2
    if (tid < GC) {
        const float HL2E = 0.7213475204444817f;
        float cc[2][2];
#pragma unroll
        for (int k = 0; k < 2; ++k)
#pragma unroll
            for (int d = 0; d < 2; ++d) {
                float p  = lsp[d * 2 + k];
                float sp = (p > 20.f) ? p : log1pf(expf(p));
                float iv = 1.f / (1e-5f + sp);
                cc[k][d] = -HL2E * iv * iv;
            }
        float2 xgv = __ldg((const float2*)xg_all + (size_t)b * NG + gc * GC + tid);
        float s0 = xgv.x * xgv.x, s1 = xgv.y * xgv.y;
        float Bg0 = fmaf(s0, cc[0][0], s1 * cc[0][1]);
        float Bg1 = fmaf(s0, cc[1][0], s1 * cc[1][1]);
        ((float4*)(tile + 32 * ZROW))[tid] = make_float4(xgv.x, xgv.y, Bg0, Bg1);
    }
}

// ---------------- main: factored weights + HMMA, cp.async double buffer ------
__global__ void __launch_bounds__(NTHREADS, 2)
setconv_h(const float* __restrict__ xt_all,
          const float* __restrict__ lsp,
          float* __restrict__ out_all)
{
    __shared__ __align__(16) u32 smem[2 * TILE_U32];   // 35840 B; reused as red buf

    const int cta  = blockIdx.x;        // 256 CTAs
    const int b    = cta >> 6;
    const int t0   = (cta & 63) * MT;
    const int tid  = threadIdx.x;
    const int w    = tid >> 5;
    const int lane = tid & 31;
    const int tsub = w >> 2;            // 0..1
    const int kk   = (w >> 1) & 1;      // RBF kernel index
    const int gs   = w & 1;             // g-split half
    const int q    = lane >> 2;         // 0..7
    const int r    = lane & 3;          // 0..3

    const u32 sbase = smem_u32(smem);
    const char* gtiles = (const char*)(g_Zh + (size_t)b * NCHUNK * TILE_U32);

    // RBF coefficients for this warp's k
    float cc0, cc1;
    {
        const float HL2E = 0.7213475204444817f;
        float p0 = lsp[0 * 2 + kk], p1 = lsp[1 * 2 + kk];
        float sp0 = (p0 > 20.f) ? p0 : log1pf(expf(p0));
        float sp1 = (p1 > 20.f) ? p1 : log1pf(expf(p1));
        float i0 = 1.f / (1e-5f + sp0), i1 = 1.f / (1e-5f + sp1);
        cc0 = -HL2E * i0 * i0;
        cc1 = -HL2E * i1 * i1;
    }

    const int tA = t0 + tsub * 16 + q;
    const int tB = tA + 8;
    const float2 xA = ((const float2*)xt_all)[(size_t)b * NT + tA];
    const float2 xB = ((const float2*)xt_all)[(size_t)b * NT + tB];

    // per-thread weight constants: arg = At + u0*xg0 + u1*xg1 + Bg
    const float AtA = fmaf(xA.x * xA.x, cc0, xA.y * xA.y * cc1);
    const float AtB = fmaf(xB.x * xB.x, cc0, xB.y * xB.y * cc1);
    const float u0A = -2.f * cc0 * xA.x, u1A = -2.f * cc1 * xA.y;
    const float u0B = -2.f * cc0 * xB.x, u1B = -2.f * cc1 * xB.y;

    // hoisted smem offsets (u32 units, stage-relative)
    const u32* zb_bu0 = smem + (gs * 8 + r) * ZROW + q * 16;   // slice s=gs
    const u32* zb_bu1 = zb_bu0 + 16 * ZROW;                    // slice s=gs+2
    const float4* zb_gm0 = (const float4*)(smem + 32 * ZROW) + gs * 16 + 2 * r;
    const float4* zb_gm1 = zb_gm0 + 32;

    float c[16][4];
#pragma unroll
    for (int j = 0; j < 16; ++j) { c[j][0]=0.f; c[j][1]=0.f; c[j][2]=0.f; c[j][3]=0.f; }

    const bool cpth = (tid < 224);
    const char* gsrc = gtiles + (size_t)tid * 16;   // chunk 0 src base

    // prologue: stage chunk 0 into stage 0
    if (cpth) {
#pragma unroll
        for (int i = 0; i < 5; ++i)
            asm volatile("cp.async.cg.shared.global [%0], [%1], 16;"
                         :: "r"(sbase + tid * 16 + i * 3584), "l"(gsrc + i * 3584) : "memory");
        asm volatile("cp.async.commit_group;" ::: "memory");
    }
    gsrc += TILE_BYTES;   // now points at chunk 1

#define CHUNK_BODY(STAGE, GCN)                                                          \
    {                                                                                   \
        asm volatile("cp.async.wait_group 0;" ::: "memory");                            \
        __syncthreads();                                                                \
        if ((GCN) < NCHUNK && cpth) {                                                   \
            const u32 dstb = sbase + (1 - (STAGE)) * TILE_BYTES + tid * 16;             \
            _Pragma("unroll")                                                           \
            for (int i = 0; i < 5; ++i)                                                 \
                asm volatile("cp.async.cg.shared.global [%0], [%1], 16;"                \
                             :: "r"(dstb + i * 3584), "l"(gsrc + i * 3584) : "memory"); \
            asm volatile("cp.async.commit_group;" ::: "memory");                        \
        }                                                                               \
        gsrc += TILE_BYTES;                                                             \
        _Pragma("unroll")                                                               \
        for (int i = 0; i < 2; ++i) {                                                   \
            const uint4* bup = (const uint4*)((i ? zb_bu1 : zb_bu0) + (STAGE) * TILE_U32); \
            const uint4* blp = bup + ZROW;   /* +4*ZROW u32 = +ZROW uint4 */            \
            uint4 BU[4], BL[4];                                                         \
            _Pragma("unroll")                                                           \
            for (int m = 0; m < 4; ++m) { BU[m] = bup[m]; BL[m] = blp[m]; }             \
            const float4* gm = (i ? zb_gm1 : zb_gm0) + (STAGE) * (TILE_U32 / 4);        \
            float4 m0 = gm[0], m1 = gm[1], m2 = gm[8], m3 = gm[9];                      \
            float B0 = kk ? m0.w : m0.z;                                                \
            float B1 = kk ? m1.w : m1.z;                                                \
            float B2 = kk ? m2.w : m2.z;                                                \
            float B3 = kk ? m3.w : m3.z;                                                \
            float wA0 = ex2f(fmaf(m0.x, u0A, fmaf(m0.y, u1A, B0)) + AtA);               \
            float wA1 = ex2f(fmaf(m1.x, u0A, fmaf(m1.y, u1A, B1)) + AtA);               \
            float wB0 = ex2f(fmaf(m0.x, u0B, fmaf(m0.y, u1B, B0)) + AtB);               \
            float wB1 = ex2f(fmaf(m1.x, u0B, fmaf(m1.y, u1B, B1)) + AtB);               \
            float wA2 = ex2f(fmaf(m2.x, u0A, fmaf(m2.y, u1A, B2)) + AtA);               \
            float wA3 = ex2f(fmaf(m3.x, u0A, fmaf(m3.y, u1A, B3)) + AtA);               \
            float wB2 = ex2f(fmaf(m2.x, u0B, fmaf(m2.y, u1B, B2)) + AtB);               \
            float wB3 = ex2f(fmaf(m3.x, u0B, fmaf(m3.y, u1B, B3)) + AtB);               \
            u32 a0 = f16x2(wA0, wA1);                                                   \
            u32 a1 = f16x2(wB0, wB1);                                                   \
            u32 a2 = f16x2(wA2, wA3);                                                   \
            u32 a3 = f16x2(wB2, wB3);                                                   \
            _Pragma("unroll")                                                           \
            for (int j = 0; j < 16; ++j) {                                              \
                u32 b0 = ((const u32*)BU)[j];                                           \
                u32 b1 = ((const u32*)BL)[j];                                           \
                asm volatile(                                                           \
                    "mma.sync.aligned.m16n8k16.row.col.f32.f16.f16.f32 "                \
                    "{%0,%1,%2,%3}, {%4,%5,%6,%7}, {%8,%9}, {%0,%1,%2,%3};"             \
                    : "+f"(c[j][0]), "+f"(c[j][1]), "+f"(c[j][2]), "+f"(c[j][3])        \
                    : "r"(a0), "r"(a1), "r"(a2), "r"(a3), "r"(b0), "r"(b1));            \
            }                                                                           \
        }                                                                               \
    }

    for (int gc = 0; gc < NCHUNK; gc += 2) {
        CHUNK_BODY(0, gc + 1)
        CHUNK_BODY(1, gc + 2)
    }

    // ---- reduce g-split pairs via smem, then store ----
    __syncthreads();
    float4* red = (float4*)smem;       // 32KB needed <= 35840 available
    const int slot = w >> 1;
    if (gs == 1) {
#pragma unroll
        for (int j = 0; j < 16; ++j)
            red[j * 128 + slot * 32 + lane] = make_float4(c[j][0], c[j][1], c[j][2], c[j][3]);
    }
    __syncthreads();
    if (gs == 0) {
        float* oA = out_all + ((size_t)b * NT + tA) * (DZ * 2) + kk;
        float* oB = out_all + ((size_t)b * NT + tB) * (DZ * 2) + kk;
#pragma unroll
        for (int j = 0; j < 16; ++j) {
            float4 v = red[j * 128 + slot * 32 + lane];
            int n0 = 16 * j + 4 * r;
            oA[n0]     = c[j][0] + v.x;
            oA[n0 + 2] = c[j][1] + v.y;
            oB[n0]     = c[j][2] + v.z;
            oB[n0 + 2] = c[j][3] + v.w;
        }
    }
}

extern "C" void kernel_launch(void* const* d_in, const int* in_sizes, int n_in,
                              void* d_out, int out_size)
{
    const float* xg  = (const float*)d_in[0];   // (4,64,64,2)
    const float* zg  = (const float*)d_in[1];   // (4,64,64,128)
    const float* xt  = (const float*)d_in[2];   // (4,2048,2)
    const float* lsp = (const float*)d_in[3];   // (2,2)
    float* out = (float*)d_out;                 // (4,2048,256)

    prep_tiles<<<NB * NCHUNK, NTHREADS>>>(zg, xg, lsp);
    setconv_h<<<NB * (NT / MT), NTHREADS>>>(xt, lsp, out);
}

// round 8
// speedup vs baseline: 7.8643x; 1.0343x over previous
#include <cuda_runtime.h>
#include <cstdint>

// Shapes (fixed)
#define NB 4
#define NG 4096
#define DZ 128
#define NT 2048

// Tiling
#define MT 32              // t rows per CTA (2 m16 tiles per warp)
#define GC 64              // g per chunk
#define NCHUNK (NG/GC)     // 64
#define ZROW 132           // u32 stride per g-pair row (pad 4 -> conflict-free)
#define TILE_U32 4608      // 32*ZROW (4224) + gmeta 256 + pad 128 = 128thr*9*4
#define TILE_BYTES (TILE_U32*4)     // 18432
#define NTHREADS 128       // 4 warps: 2 kk x 2 gs
#define PTHREADS 256

typedef unsigned int u32;

// Pre-packed tiles: [b][chunk][ Z f16x2 32xZROW | gmeta 64 x {xg0,xg1,Bg0,Bg1} | pad ]
__device__ __align__(16) u32 g_Zh[(size_t)NB * NCHUNK * TILE_U32];

__device__ __forceinline__ float ex2f(float x) {
    float y; asm("ex2.approx.f32 %0, %1;" : "=f"(y) : "f"(x)); return y;
}
__device__ __forceinline__ u32 f16x2(float lo, float hi) {
    u32 d; asm("cvt.rn.f16x2.f32 %0, %1, %2;" : "=r"(d) : "f"(hi), "f"(lo)); return d;
}
__device__ __forceinline__ u32 smem_u32(const void* p) {
    u32 a;
    asm("{ .reg .u64 t; cvta.to.shared.u64 t, %1; cvt.u32.u64 %0, t; }" : "=r"(a) : "l"(p));
    return a;
}

// ---------------- prep: pack Z (f16x2, g-pairs, j-permuted) + gmeta ----------
__global__ void __launch_bounds__(PTHREADS)
prep_tiles(const float* __restrict__ zg_all, const float* __restrict__ xg_all,
           const float* __restrict__ lsp)
{
    const int bc  = blockIdx.x;          // b*NCHUNK + chunk
    const int b   = bc >> 6;
    const int gc  = bc & 63;
    const int tid = threadIdx.x;
    const int w   = tid >> 5;
    const int z4  = tid & 31;

    u32* tile = g_Zh + (size_t)bc * TILE_U32;
    const float* zbase = zg_all + ((size_t)b * NG + gc * GC) * DZ;

#pragma unroll
    for (int it = 0; it < 4; ++it) {
        int gp = w + it * 8;             // 0..31 (g-pair)
        float4 v0 = __ldg((const float4*)(zbase + (size_t)(2 * gp)     * DZ) + z4);
        float4 v1 = __ldg((const float4*)(zbase + (size_t)(2 * gp + 1) * DZ) + z4);
        u32* dst = tile + gp * ZROW;
        int p0 = (z4 & 1) * 64 + (z4 >> 1);     // perm p(z)=(z&7)*16+(z>>3)
        dst[p0]      = f16x2(v0.x, v1.x);
        dst[p0 + 16] = f16x2(v0.y, v1.y);
        dst[p0 + 32] = f16x2(v0.z, v1.z);
        dst[p0 + 48] = f16x2(v0.w, v1.w);
    }

    // gmeta: per g {xg0, xg1, Bg_k0, Bg_k1}, Bg_k = ck0*xg0^2 + ck1*xg1^2
    if (tid < GC) {
        const float HL2E = 0.7213475204444817f;
        float cc[2][2];
#pragma unroll
        for (int k = 0; k < 2; ++k)
#pragma unroll
            for (int d = 0; d < 2; ++d) {
                float p  = lsp[d * 2 + k];
                float sp = (p > 20.f) ? p : log1pf(expf(p));
                float iv = 1.f / (1e-5f + sp);
                cc[k][d] = -HL2E * iv * iv;
            }
        float2 xgv = __ldg((const float2*)xg_all + (size_t)b * NG + gc * GC + tid);
        float s0 = xgv.x * xgv.x, s1 = xgv.y * xgv.y;
        float Bg0 = fmaf(s0, cc[0][0], s1 * cc[0][1]);
        float Bg1 = fmaf(s0, cc[1][0], s1 * cc[1][1]);
        ((float4*)(tile + 32 * ZROW))[tid] = make_float4(xgv.x, xgv.y, Bg0, Bg1);
    }
}

// -------- per-chunk compute: B loaded once, reused by 2 M-tiles --------------
__device__ __forceinline__ void do_chunk(
    const u32* bu0, const u32* bu1, const float4* gm0, const float4* gm1,
    int kk, const float* At, const float* u0, const float* u1,
    float (&c)[2][16][4])
{
#pragma unroll
    for (int i = 0; i < 2; ++i) {
        const uint4* bup = (const uint4*)(i ? bu1 : bu0);
        const uint4* blp = bup + ZROW;    // +4*ZROW u32
        uint4 BU[4], BL[4];
#pragma unroll
        for (int m = 0; m < 4; ++m) { BU[m] = bup[m]; BL[m] = blp[m]; }

        const float4* gm = i ? gm1 : gm0;
        float4 m0 = gm[0], m1 = gm[1], m2 = gm[8], m3 = gm[9];
        float B0 = kk ? m0.w : m0.z;
        float B1 = kk ? m1.w : m1.z;
        float B2 = kk ? m2.w : m2.z;
        float B3 = kk ? m3.w : m3.z;

        // weights for 4 rows x 4 g-cols
        float wv[4][4];
#pragma unroll
        for (int rr = 0; rr < 4; ++rr) {
            wv[rr][0] = ex2f(fmaf(m0.x, u0[rr], fmaf(m0.y, u1[rr], B0)) + At[rr]);
            wv[rr][1] = ex2f(fmaf(m1.x, u0[rr], fmaf(m1.y, u1[rr], B1)) + At[rr]);
            wv[rr][2] = ex2f(fmaf(m2.x, u0[rr], fmaf(m2.y, u1[rr], B2)) + At[rr]);
            wv[rr][3] = ex2f(fmaf(m3.x, u0[rr], fmaf(m3.y, u1[rr], B3)) + At[rr]);
        }
        u32 a[2][4];
#pragma unroll
        for (int m = 0; m < 2; ++m) {
            a[m][0] = f16x2(wv[2*m][0],   wv[2*m][1]);
            a[m][1] = f16x2(wv[2*m+1][0], wv[2*m+1][1]);
            a[m][2] = f16x2(wv[2*m][2],   wv[2*m][3]);
            a[m][3] = f16x2(wv[2*m+1][2], wv[2*m+1][3]);
        }
#pragma unroll
        for (int j = 0; j < 16; ++j) {
            u32 b0 = ((const u32*)BU)[j];
            u32 b1 = ((const u32*)BL)[j];
#pragma unroll
            for (int m = 0; m < 2; ++m)
                asm volatile(
                    "mma.sync.aligned.m16n8k16.row.col.f32.f16.f16.f32 "
                    "{%0,%1,%2,%3}, {%4,%5,%6,%7}, {%8,%9}, {%0,%1,%2,%3};"
                    : "+f"(c[m][j][0]), "+f"(c[m][j][1]), "+f"(c[m][j][2]), "+f"(c[m][j][3])
                    : "r"(a[m][0]), "r"(a[m][1]), "r"(a[m][2]), "r"(a[m][3]),
                      "r"(b0), "r"(b1));
        }
    }
}

// ---------------- main: factored weights + HMMA, cp.async double buffer ------
__global__ void __launch_bounds__(NTHREADS, 2)
setconv_h(const float* __restrict__ xt_all,
          const float* __restrict__ lsp,
          float* __restrict__ out_all)
{
    __shared__ __align__(16) u32 smem[2 * TILE_U32];   // 36864 B; reused as red buf

    const int cta  = blockIdx.x;        // 256 CTAs
    const int b    = cta >> 6;
    const int t0   = (cta & 63) * MT;
    const int tid  = threadIdx.x;
    const int w    = tid >> 5;          // 0..3
    const int lane = tid & 31;
    const int kk   = w >> 1;            // RBF kernel index
    const int gs   = w & 1;             // g-split half
    const int q    = lane >> 2;         // 0..7
    const int r    = lane & 3;          // 0..3

    const u32 sbase = smem_u32(smem);
    const char* gtiles = (const char*)(g_Zh + (size_t)b * NCHUNK * TILE_U32);

    // RBF coefficients for this warp's k
    float cc0, cc1;
    {
        const float HL2E = 0.7213475204444817f;
        float p0 = lsp[0 * 2 + kk], p1 = lsp[1 * 2 + kk];
        float sp0 = (p0 > 20.f) ? p0 : log1pf(expf(p0));
        float sp1 = (p1 > 20.f) ? p1 : log1pf(expf(p1));
        float i0 = 1.f / (1e-5f + sp0), i1 = 1.f / (1e-5f + sp1);
        cc0 = -HL2E * i0 * i0;
        cc1 = -HL2E * i1 * i1;
    }

    // 4 rows: [0]=t0+q, [1]=t0+8+q (tile0); [2]=t0+16+q, [3]=t0+24+q (tile1)
    float At[4], u0[4], u1[4];
#pragma unroll
    for (int rr = 0; rr < 4; ++rr) {
        float2 xv = ((const float2*)xt_all)[(size_t)b * NT + t0 + rr * 8 + q];
        At[rr] = fmaf(xv.x * xv.x, cc0, xv.y * xv.y * cc1);
        u0[rr] = -2.f * cc0 * xv.x;
        u1[rr] = -2.f * cc1 * xv.y;
    }

    // hoisted smem offsets (stage 0)
    const u32* zb_bu0 = smem + (gs * 8 + r) * ZROW + q * 16;   // slice s=gs
    const u32* zb_bu1 = zb_bu0 + 16 * ZROW;                    // slice s=gs+2
    const float4* zb_gm0 = (const float4*)(smem + 32 * ZROW) + gs * 16 + 2 * r;
    const float4* zb_gm1 = zb_gm0 + 32;

    float c[2][16][4];
#pragma unroll
    for (int m = 0; m < 2; ++m)
#pragma unroll
        for (int j = 0; j < 16; ++j) {
            c[m][j][0] = 0.f; c[m][j][1] = 0.f; c[m][j][2] = 0.f; c[m][j][3] = 0.f;
        }

    const char* gsrc = gtiles + (size_t)tid * 16;   // chunk 0 src base

    // prologue: stage chunk 0 into stage 0 (9 segs x 2048B stride)
#pragma unroll
    for (int i = 0; i < 9; ++i)
        asm volatile("cp.async.cg.shared.global [%0], [%1], 16;"
                     :: "r"(sbase + tid * 16 + i * 2048), "l"(gsrc + i * 2048) : "memory");
    asm volatile("cp.async.commit_group;" ::: "memory");
    gsrc += TILE_BYTES;

#pragma unroll 1
    for (int gc = 0; gc < NCHUNK; gc += 2) {
#pragma unroll
        for (int st = 0; st < 2; ++st) {
            asm volatile("cp.async.wait_group 0;" ::: "memory");
            __syncthreads();
            if (gc + 1 + st < NCHUNK) {
                const u32 dstb = sbase + (1 - st) * TILE_BYTES + tid * 16;
#pragma unroll
                for (int i = 0; i < 9; ++i)
                    asm volatile("cp.async.cg.shared.global [%0], [%1], 16;"
                                 :: "r"(dstb + i * 2048), "l"(gsrc + i * 2048) : "memory");
                asm volatile("cp.async.commit_group;" ::: "memory");
            }
            gsrc += TILE_BYTES;
            do_chunk(zb_bu0 + st * TILE_U32, zb_bu1 + st * TILE_U32,
                     zb_gm0 + st * (TILE_U32 / 4), zb_gm1 + st * (TILE_U32 / 4),
                     kk, At, u0, u1, c);
        }
    }

    // ---- reduce g-split pairs via smem, then store ----
    __syncthreads();
    float4* red = (float4*)smem;       // 32KB needed <= 36864 available
    if (gs == 1) {
#pragma unroll
        for (int m = 0; m < 2; ++m)
#pragma unroll
            for (int j = 0; j < 16; ++j)
                red[((kk * 2 + m) * 16 + j) * 32 + lane] =
                    make_float4(c[m][j][0], c[m][j][1], c[m][j][2], c[m][j][3]);
    }
    __syncthreads();
    if (gs == 0) {
#pragma unroll
        for (int m = 0; m < 2; ++m) {
            float* oA = out_all + ((size_t)b * NT + t0 + m * 16 + q) * (DZ * 2) + kk;
            float* oB = oA + 8 * (DZ * 2);
#pragma unroll
            for (int j = 0; j < 16; ++j) {
                float4 v = red[((kk * 2 + m) * 16 + j) * 32 + lane];
                int n0 = 16 * j + 4 * r;
                oA[n0]     = c[m][j][0] + v.x;
                oA[n0 + 2] = c[m][j][1] + v.y;
                oB[n0]     = c[m][j][2] + v.z;
                oB[n0 + 2] = c[m][j][3] + v.w;
            }
        }
    }
}

extern "C" void kernel_launch(void* const* d_in, const int* in_sizes, int n_in,
                              void* d_out, int out_size)
{
    const float* xg  = (const float*)d_in[0];   // (4,64,64,2)
    const float* zg  = (const float*)d_in[1];   // (4,64,64,128)
    const float* xt  = (const float*)d_in[2];   // (4,2048,2)
    const float* lsp = (const float*)d_in[3];   // (2,2)
    float* out = (float*)d_out;                 // (4,2048,256)

    prep_tiles<<<NB * NCHUNK, PTHREADS>>>(zg, xg, lsp);
    setconv_h<<<NB * (NT / MT), NTHREADS>>>(xt, lsp, out);
}